// round 1
// baseline (speedup 1.0000x reference)
#include <cuda_runtime.h>
#include <stdint.h>

// Problem constants (fixed shapes from reference)
#define SS 8192      // seq len
#define KK 4096      // keep_k
#define DD 2048      // hidden dim
#define LL 8         // layers
#define HH 16        // heads
#define HD 128       // head dim

// Output layout (flat float32, concatenation of the 5 returned tensors):
//   [0 .. 8388608)                 pruned_hidden  [1,4096,2048]
//   [8388608 .. 8392704)           pruned_mask    [1,4096]
//   [8392704 .. 8396800)           idx            [1,4096]
//   [8396800 .. 75505664)          pruned_keys    [8,1,16,4096,128]
//   [75505664 .. 142614528)        pruned_values  [8,1,16,4096,128]
#define OFF_MASK   8388608
#define OFF_IDX    8392704
#define OFF_KEYS4  2099200LL    // 8396800 / 4   (float4 units)
#define OFF_VALS4  18876416LL   // 75505664 / 4  (float4 units)

#define H4  2097152LL           // hidden float4 count: 4096*2048/4
#define KV4 16777216LL          // keys float4 count: 8*16*4096*128/4
#define TOTAL4 (H4 + 2*KV4)     // 35,651,584

__device__ int g_idx[KK];

__device__ __forceinline__ unsigned f2u(float f) {
    unsigned u = __float_as_uint(f);
    // monotonic map: larger float -> larger uint
    return u ^ ((u >> 31) ? 0xFFFFFFFFu : 0x80000000u);
}

// -------------------------------------------------------------------------
// Kernel 1: single block. Radix-select the K-th largest score, then a block
// prefix-scan in token order emits the kept indices already sorted ascending.
// -------------------------------------------------------------------------
__global__ __launch_bounds__(1024, 1)
void topk_kernel(const float* __restrict__ scores,
                 const int*   __restrict__ attn_mask,
                 float*       __restrict__ out)
{
    __shared__ unsigned skey[SS];
    __shared__ unsigned red_warp[32];
    __shared__ unsigned warp_gt[32], warp_eq[32];
    __shared__ unsigned s_prefix, s_krem;

    const int tid = threadIdx.x;

    // load + order-preserving transform
    for (int i = tid; i < SS; i += 1024) skey[i] = f2u(scores[i]);
    if (tid == 0) { s_prefix = 0u; s_krem = KK; }
    __syncthreads();

    // MSB-first radix select of the K-th largest key (exact value)
    for (int bit = 31; bit >= 0; --bit) {
        const unsigned prefix = s_prefix;
        const unsigned maskhi = (bit == 31) ? 0u : (0xFFFFFFFFu << (bit + 1));
        unsigned c = 0;
        #pragma unroll
        for (int j = 0; j < SS / 1024; ++j) {
            unsigned k = skey[tid + j * 1024];
            c += (((k & maskhi) == prefix) && ((k >> bit) & 1u)) ? 1u : 0u;
        }
        #pragma unroll
        for (int o = 16; o; o >>= 1) c += __shfl_down_sync(0xffffffffu, c, o);
        if ((tid & 31) == 0) red_warp[tid >> 5] = c;
        __syncthreads();
        if (tid == 0) {
            unsigned tot = 0;
            #pragma unroll
            for (int w = 0; w < 32; ++w) tot += red_warp[w];
            if (tot >= s_krem) s_prefix = prefix | (1u << bit);
            else               s_krem  -= tot;
        }
        __syncthreads();
    }
    const unsigned T    = s_prefix;   // exact K-th largest key
    const unsigned need = s_krem;     // how many ==T entries to keep (lowest idx first)

    // Per-thread local counts over 8 consecutive tokens
    const int base = tid * 8;
    unsigned lg = 0, le = 0;
    #pragma unroll
    for (int j = 0; j < 8; ++j) {
        unsigned k = skey[base + j];
        lg += (k > T);
        le += (k == T);
    }
    // inclusive warp scans
    unsigned eg = lg, ee = le;
    #pragma unroll
    for (int o = 1; o < 32; o <<= 1) {
        unsigned tg = __shfl_up_sync(0xffffffffu, eg, o);
        unsigned te = __shfl_up_sync(0xffffffffu, ee, o);
        if ((tid & 31) >= o) { eg += tg; ee += te; }
    }
    if ((tid & 31) == 31) { warp_gt[tid >> 5] = eg; warp_eq[tid >> 5] = ee; }
    __syncthreads();
    if (tid < 32) {
        unsigned g = warp_gt[tid], e = warp_eq[tid];
        #pragma unroll
        for (int o = 1; o < 32; o <<= 1) {
            unsigned tg = __shfl_up_sync(0xffffffffu, g, o);
            unsigned te = __shfl_up_sync(0xffffffffu, e, o);
            if (tid >= o) { g += tg; e += te; }
        }
        warp_gt[tid] = g; warp_eq[tid] = e;  // inclusive over warp totals
    }
    __syncthreads();

    const int w = tid >> 5;
    unsigned gt_before = ((w == 0) ? 0u : warp_gt[w - 1]) + (eg - lg);
    unsigned eq_before = ((w == 0) ? 0u : warp_eq[w - 1]) + (ee - le);

    #pragma unroll
    for (int j = 0; j < 8; ++j) {
        const int i = base + j;
        unsigned k = skey[i];
        bool gt = (k > T);
        bool eq = (k == T);
        bool sel = gt || (eq && (eq_before < need));
        if (sel) {
            unsigned pos = gt_before + min(eq_before, need);
            g_idx[pos] = i;
            out[OFF_IDX  + pos] = (float)i;
            out[OFF_MASK + pos] = (float)attn_mask[i];
        }
        gt_before += gt ? 1u : 0u;
        eq_before += eq ? 1u : 0u;
    }
}

// -------------------------------------------------------------------------
// Kernel 2: flat float4 gather over hidden / keys / values.
// KV rows are 512B (32 float4) => one warp per row, g_idx load warp-uniform.
// -------------------------------------------------------------------------
__global__ __launch_bounds__(256)
void gather_kernel(const float4* __restrict__ hidden,
                   const float4* __restrict__ keys,
                   const float4* __restrict__ values,
                   float4*       __restrict__ out)
{
    long long e = (long long)blockIdx.x * 256 + threadIdx.x;
    if (e < H4) {
        // hidden: rows of 512 float4 (8KB), contiguous copy
        int lane = (int)(e & 511);
        int k    = (int)(e >> 9);
        int src  = g_idx[k];
        out[e] = hidden[(long long)src * 512 + lane];
    } else if (e < H4 + KV4) {
        long long t   = e - H4;
        int lane      = (int)(t & 31);
        long long row = t >> 5;
        int k         = (int)(row & (KK - 1));
        long long lh  = row >> 12;                // layer*H + head, 0..127
        int src       = g_idx[k];
        out[OFF_KEYS4 + t] = keys[(lh * SS + src) * 32 + lane];
    } else {
        long long t   = e - H4 - KV4;
        int lane      = (int)(t & 31);
        long long row = t >> 5;
        int k         = (int)(row & (KK - 1));
        long long lh  = row >> 12;
        int src       = g_idx[k];
        out[OFF_VALS4 + t] = values[(lh * SS + src) * 32 + lane];
    }
}

extern "C" void kernel_launch(void* const* d_in, const int* in_sizes, int n_in,
                              void* d_out, int out_size)
{
    const float* hidden = (const float*)d_in[0];   // [1,8192,2048] f32
    const float* scores = (const float*)d_in[1];   // [1,8192] f32
    const int*   amask  = (const int*)  d_in[2];   // [1,8192] i32
    const float* keys   = (const float*)d_in[3];   // [8,1,16,8192,128] f32
    const float* values = (const float*)d_in[4];   // [8,1,16,8192,128] f32
    float* out = (float*)d_out;

    topk_kernel<<<1, 1024>>>(scores, amask, out);

    const long long total4 = TOTAL4;               // 35,651,584 -> exact /256
    int blocks = (int)(total4 / 256);
    gather_kernel<<<blocks, 256>>>((const float4*)hidden,
                                   (const float4*)keys,
                                   (const float4*)values,
                                   (float4*)out);
}

// round 4
// speedup vs baseline: 1.1358x; 1.1358x over previous
#include <cuda_runtime.h>
#include <stdint.h>

// Problem constants (fixed shapes from reference)
#define SS 8192      // seq len
#define KK 4096      // keep_k
#define DD 2048      // hidden dim

// Output layout (flat float32):
//   [0 .. 8388608)         pruned_hidden  [1,4096,2048]
//   [8388608 .. 8392704)   pruned_mask    [1,4096]
//   [8392704 .. 8396800)   idx            [1,4096]
//   [8396800 .. 75505664)  pruned_keys    [8,1,16,4096,128]
//   [75505664 ..142614528) pruned_values  [8,1,16,4096,128]
#define OFF_MASK   8388608
#define OFF_IDX    8392704
#define OFF_KEYS4  2099200LL    // /4 (float4 units)
#define OFF_VALS4  18876416LL

#define H4  2097152LL           // hidden float4 count
#define KV4 16777216LL          // keys float4 count
#define TOTAL4 (H4 + 2*KV4)     // 35,651,584  (divisible by 1024)

__device__ int g_idx[KK];

__device__ __forceinline__ unsigned f2u(float f) {
    unsigned u = __float_as_uint(f);
    return u ^ ((u >> 31) ? 0xFFFFFFFFu : 0x80000000u);
}

// -------------------------------------------------------------------------
// Kernel 1: single block. 4-pass 256-bin histogram select of the K-th
// largest key, then a block prefix-scan in token order emits kept indices
// already sorted ascending.
// -------------------------------------------------------------------------
__global__ __launch_bounds__(1024, 1)
void topk_kernel(const float* __restrict__ scores,
                 const int*   __restrict__ attn_mask,
                 float*       __restrict__ out)
{
    __shared__ unsigned skey[SS];
    __shared__ unsigned hist[256];
    __shared__ unsigned warp_gt[32], warp_eq[32];
    __shared__ unsigned s_prefix, s_krem;

    const int tid = threadIdx.x;

    for (int i = tid; i < SS; i += 1024) skey[i] = f2u(scores[i]);
    if (tid == 0) { s_prefix = 0u; s_krem = KK; }

    // ---- 4 passes of 8-bit histogram select (MSB first) ----
    #pragma unroll
    for (int pass = 0; pass < 4; ++pass) {
        const int shift = 24 - 8 * pass;
        if (tid < 256) hist[tid] = 0u;
        __syncthreads();
        const unsigned prefix = s_prefix;
        const unsigned maskhi = (pass == 0) ? 0u : (0xFFFFFFFFu << (shift + 8));
        #pragma unroll
        for (int j = 0; j < SS / 1024; ++j) {
            unsigned k = skey[tid + j * 1024];
            if ((k & maskhi) == prefix) atomicAdd(&hist[(k >> shift) & 255u], 1u);
        }
        __syncthreads();
        if (tid < 32) {
            // lane covers 8 bins in DESCENDING bin order
            unsigned local[8], lsum = 0;
            #pragma unroll
            for (int j = 0; j < 8; ++j) { local[j] = hist[255 - (tid * 8 + j)]; lsum += local[j]; }
            unsigned incl = lsum;
            #pragma unroll
            for (int o = 1; o < 32; o <<= 1) {
                unsigned t = __shfl_up_sync(0xffffffffu, incl, o);
                if (tid >= o) incl += t;
            }
            unsigned excl = incl - lsum;
            unsigned krem = s_krem;
            if (excl < krem && incl >= krem) {   // exactly one lane
                unsigned rem = krem - excl;
                #pragma unroll
                for (int j = 0; j < 8; ++j) {
                    if (local[j] >= rem) {
                        s_prefix = prefix | ((unsigned)(255 - (tid * 8 + j)) << shift);
                        s_krem = rem;
                        break;
                    }
                    rem -= local[j];
                }
            }
        }
        __syncthreads();
    }
    const unsigned T    = s_prefix;   // exact K-th largest key
    const unsigned need = s_krem;     // how many ==T entries to keep (lowest idx first)

    // ---- ordered emit via block prefix scan over (>,==) counts ----
    const int base = tid * 8;
    unsigned lg = 0, le = 0;
    #pragma unroll
    for (int j = 0; j < 8; ++j) {
        unsigned k = skey[base + j];
        lg += (k > T);
        le += (k == T);
    }
    unsigned eg = lg, ee = le;
    #pragma unroll
    for (int o = 1; o < 32; o <<= 1) {
        unsigned tg = __shfl_up_sync(0xffffffffu, eg, o);
        unsigned te = __shfl_up_sync(0xffffffffu, ee, o);
        if ((tid & 31) >= o) { eg += tg; ee += te; }
    }
    if ((tid & 31) == 31) { warp_gt[tid >> 5] = eg; warp_eq[tid >> 5] = ee; }
    __syncthreads();
    if (tid < 32) {
        unsigned g = warp_gt[tid], e = warp_eq[tid];
        #pragma unroll
        for (int o = 1; o < 32; o <<= 1) {
            unsigned tg = __shfl_up_sync(0xffffffffu, g, o);
            unsigned te = __shfl_up_sync(0xffffffffu, e, o);
            if (tid >= o) { g += tg; e += te; }
        }
        warp_gt[tid] = g; warp_eq[tid] = e;
    }
    __syncthreads();

    const int w = tid >> 5;
    unsigned gt_before = ((w == 0) ? 0u : warp_gt[w - 1]) + (eg - lg);
    unsigned eq_before = ((w == 0) ? 0u : warp_eq[w - 1]) + (ee - le);

    #pragma unroll
    for (int j = 0; j < 8; ++j) {
        const int i = base + j;
        unsigned k = skey[i];
        bool gt = (k > T);
        bool eq = (k == T);
        bool sel = gt || (eq && (eq_before < need));
        if (sel) {
            unsigned pos = gt_before + min(eq_before, need);
            g_idx[pos] = i;
            out[OFF_IDX  + pos] = (float)i;
            out[OFF_MASK + pos] = (float)attn_mask[i];
        }
        gt_before += gt ? 1u : 0u;
        eq_before += eq ? 1u : 0u;
    }
}

// -------------------------------------------------------------------------
// Kernel 2: flat float4 gather over hidden / keys / values.
// 4 float4 per thread (MLP=4), streaming cache hints (data touched once).
// Each 1024-float4 block lies entirely within one region.
// -------------------------------------------------------------------------
__global__ __launch_bounds__(256)
void gather_kernel(const float4* __restrict__ hidden,
                   const float4* __restrict__ keys,
                   const float4* __restrict__ values,
                   float4*       __restrict__ out)
{
    const long long blk = (long long)blockIdx.x * 1024;
    const float4* src[4];
    float4*       dst[4];
    #pragma unroll
    for (int it = 0; it < 4; ++it) {
        long long e = blk + it * 256 + threadIdx.x;
        if (e < H4) {
            int lane = (int)(e & 511);
            int k    = (int)(e >> 9);
            int s    = g_idx[k];
            src[it] = &hidden[(long long)s * 512 + lane];
            dst[it] = &out[e];
        } else if (e < H4 + KV4) {
            long long t   = e - H4;
            int lane      = (int)(t & 31);
            long long row = t >> 5;
            int k         = (int)(row & (KK - 1));
            long long lh  = row >> 12;
            int s         = g_idx[k];
            src[it] = &keys[(lh * SS + s) * 32 + lane];
            dst[it] = &out[OFF_KEYS4 + t];
        } else {
            long long t   = e - H4 - KV4;
            int lane      = (int)(t & 31);
            long long row = t >> 5;
            int k         = (int)(row & (KK - 1));
            long long lh  = row >> 12;
            int s         = g_idx[k];
            src[it] = &values[(lh * SS + s) * 32 + lane];
            dst[it] = &out[OFF_VALS4 + t];
        }
    }
    float4 v[4];
    #pragma unroll
    for (int it = 0; it < 4; ++it) v[it] = __ldcs(src[it]);
    #pragma unroll
    for (int it = 0; it < 4; ++it) __stcs(dst[it], v[it]);
}

extern "C" void kernel_launch(void* const* d_in, const int* in_sizes, int n_in,
                              void* d_out, int out_size)
{
    const float* hidden = (const float*)d_in[0];   // [1,8192,2048] f32
    const float* scores = (const float*)d_in[1];   // [1,8192] f32
    const int*   amask  = (const int*)  d_in[2];   // [1,8192] i32
    const float* keys   = (const float*)d_in[3];   // [8,1,16,8192,128] f32
    const float* values = (const float*)d_in[4];   // [8,1,16,8192,128] f32
    float* out = (float*)d_out;

    topk_kernel<<<1, 1024>>>(scores, amask, out);

    int blocks = (int)(TOTAL4 / 1024);             // 34816
    gather_kernel<<<blocks, 256>>>((const float4*)hidden,
                                   (const float4*)keys,
                                   (const float4*)values,
                                   (float4*)out);
}

// round 6
// speedup vs baseline: 1.1484x; 1.0111x over previous
#include <cuda_runtime.h>
#include <stdint.h>

// Problem constants (fixed shapes from reference)
#define SS 8192      // seq len
#define KK 4096      // keep_k
#define DD 2048      // hidden dim

// Output layout (flat float32):
//   [0 .. 8388608)         pruned_hidden  [1,4096,2048]
//   [8388608 .. 8392704)   pruned_mask    [1,4096]
//   [8392704 .. 8396800)   idx            [1,4096]
//   [8396800 .. 75505664)  pruned_keys    [8,1,16,4096,128]
//   [75505664 ..142614528) pruned_values  [8,1,16,4096,128]
#define OFF_MASK   8388608
#define OFF_IDX    8392704
#define OFF_KEYS4  2099200LL    // /4 (float4 units)
#define OFF_VALS4  18876416LL

#define H4  2097152LL           // hidden float4 count
#define KV4 16777216LL          // keys float4 count
#define TOTAL4 (H4 + 2*KV4)     // 35,651,584  (divisible by 1024)

__device__ int g_idx[KK];

__device__ __forceinline__ unsigned f2u(float f) {
    unsigned u = __float_as_uint(f);
    return u ^ ((u >> 31) ? 0xFFFFFFFFu : 0x80000000u);
}

// -------------------------------------------------------------------------
// Kernel 1: single block. 4-pass 256-bin histogram select of the K-th
// largest key, then a block prefix-scan in token order emits kept indices
// already sorted ascending. Triggers programmatic launch completion at
// entry so the gather grid can ramp up concurrently.
// -------------------------------------------------------------------------
__global__ __launch_bounds__(1024, 1)
void topk_kernel(const float* __restrict__ scores,
                 const int*   __restrict__ attn_mask,
                 float*       __restrict__ out)
{
    // Let the dependent gather grid start launching immediately; it gates
    // itself with cudaGridDependencySynchronize() before reading g_idx.
    cudaTriggerProgrammaticLaunchCompletion();

    __shared__ unsigned skey[SS];
    __shared__ unsigned hist[256];
    __shared__ unsigned warp_gt[32], warp_eq[32];
    __shared__ unsigned s_prefix, s_krem;

    const int tid = threadIdx.x;

    for (int i = tid; i < SS; i += 1024) skey[i] = f2u(scores[i]);
    if (tid == 0) { s_prefix = 0u; s_krem = KK; }

    // ---- 4 passes of 8-bit histogram select (MSB first) ----
    #pragma unroll
    for (int pass = 0; pass < 4; ++pass) {
        const int shift = 24 - 8 * pass;
        if (tid < 256) hist[tid] = 0u;
        __syncthreads();
        const unsigned prefix = s_prefix;
        const unsigned maskhi = (pass == 0) ? 0u : (0xFFFFFFFFu << (shift + 8));
        #pragma unroll
        for (int j = 0; j < SS / 1024; ++j) {
            unsigned k = skey[tid + j * 1024];
            if ((k & maskhi) == prefix) atomicAdd(&hist[(k >> shift) & 255u], 1u);
        }
        __syncthreads();
        if (tid < 32) {
            unsigned local[8], lsum = 0;
            #pragma unroll
            for (int j = 0; j < 8; ++j) { local[j] = hist[255 - (tid * 8 + j)]; lsum += local[j]; }
            unsigned incl = lsum;
            #pragma unroll
            for (int o = 1; o < 32; o <<= 1) {
                unsigned t = __shfl_up_sync(0xffffffffu, incl, o);
                if (tid >= o) incl += t;
            }
            unsigned excl = incl - lsum;
            unsigned krem = s_krem;
            if (excl < krem && incl >= krem) {   // exactly one lane
                unsigned rem = krem - excl;
                #pragma unroll
                for (int j = 0; j < 8; ++j) {
                    if (local[j] >= rem) {
                        s_prefix = prefix | ((unsigned)(255 - (tid * 8 + j)) << shift);
                        s_krem = rem;
                        break;
                    }
                    rem -= local[j];
                }
            }
        }
        __syncthreads();
    }
    const unsigned T    = s_prefix;   // exact K-th largest key
    const unsigned need = s_krem;     // how many ==T entries to keep (lowest idx first)

    // ---- ordered emit via block prefix scan over (>,==) counts ----
    const int base = tid * 8;
    unsigned lg = 0, le = 0;
    #pragma unroll
    for (int j = 0; j < 8; ++j) {
        unsigned k = skey[base + j];
        lg += (k > T);
        le += (k == T);
    }
    unsigned eg = lg, ee = le;
    #pragma unroll
    for (int o = 1; o < 32; o <<= 1) {
        unsigned tg = __shfl_up_sync(0xffffffffu, eg, o);
        unsigned te = __shfl_up_sync(0xffffffffu, ee, o);
        if ((tid & 31) >= o) { eg += tg; ee += te; }
    }
    if ((tid & 31) == 31) { warp_gt[tid >> 5] = eg; warp_eq[tid >> 5] = ee; }
    __syncthreads();
    if (tid < 32) {
        unsigned g = warp_gt[tid], e = warp_eq[tid];
        #pragma unroll
        for (int o = 1; o < 32; o <<= 1) {
            unsigned tg = __shfl_up_sync(0xffffffffu, g, o);
            unsigned te = __shfl_up_sync(0xffffffffu, e, o);
            if (tid >= o) { g += tg; e += te; }
        }
        warp_gt[tid] = g; warp_eq[tid] = e;
    }
    __syncthreads();

    const int w = tid >> 5;
    unsigned gt_before = ((w == 0) ? 0u : warp_gt[w - 1]) + (eg - lg);
    unsigned eq_before = ((w == 0) ? 0u : warp_eq[w - 1]) + (ee - le);

    #pragma unroll
    for (int j = 0; j < 8; ++j) {
        const int i = base + j;
        unsigned k = skey[i];
        bool gt = (k > T);
        bool eq = (k == T);
        bool sel = gt || (eq && (eq_before < need));
        if (sel) {
            unsigned pos = gt_before + min(eq_before, need);
            g_idx[pos] = i;
            out[OFF_IDX  + pos] = (float)i;
            out[OFF_MASK + pos] = (float)attn_mask[i];
        }
        gt_before += gt ? 1u : 0u;
        eq_before += eq ? 1u : 0u;
    }
}

// -------------------------------------------------------------------------
// Kernel 2: flat float4 gather over hidden / keys / values.
// Launched with Programmatic Dependent Launch: address math happens while
// topk is still running; cudaGridDependencySynchronize() gates the g_idx
// reads on full completion (memory-visible) of topk.
// -------------------------------------------------------------------------
__global__ __launch_bounds__(256)
void gather_kernel(const float4* __restrict__ hidden,
                   const float4* __restrict__ keys,
                   const float4* __restrict__ values,
                   float4*       __restrict__ out)
{
    const long long blk = (long long)blockIdx.x * 1024;
    // Pre-compute everything not depending on g_idx.
    int       kidx[4];          // which kept-row index we need
    long long rowbase[4];       // src row base (float4 units) before adding row
    float4*   dst[4];
    const float4* srcb[4];
    int       lane[4];
    #pragma unroll
    for (int it = 0; it < 4; ++it) {
        long long e = blk + it * 256 + threadIdx.x;
        if (e < H4) {
            lane[it]    = (int)(e & 511);
            kidx[it]    = (int)(e >> 9);
            rowbase[it] = 0;             // hidden: row stride 512, lh=0
            srcb[it]    = hidden;
            dst[it]     = &out[e];
        } else if (e < H4 + KV4) {
            long long t   = e - H4;
            lane[it]      = (int)(t & 31);
            long long row = t >> 5;
            kidx[it]      = (int)(row & (KK - 1));
            long long lh  = row >> 12;
            rowbase[it]   = lh * SS;     // in rows of 32 float4
            srcb[it]      = keys;
            dst[it]       = &out[OFF_KEYS4 + t];
        } else {
            long long t   = e - H4 - KV4;
            lane[it]      = (int)(t & 31);
            long long row = t >> 5;
            kidx[it]      = (int)(row & (KK - 1));
            long long lh  = row >> 12;
            rowbase[it]   = lh * SS;
            srcb[it]      = values;
            dst[it]       = &out[OFF_VALS4 + t];
        }
    }

    // Wait for topk grid to complete (g_idx fully written & visible).
    cudaGridDependencySynchronize();

    float4 v[4];
    #pragma unroll
    for (int it = 0; it < 4; ++it) {
        int s = g_idx[kidx[it]];
        const float4* p;
        if (srcb[it] == hidden)
            p = &hidden[(long long)s * 512 + lane[it]];
        else
            p = &srcb[it][(rowbase[it] + s) * 32 + lane[it]];
        v[it] = __ldcs(p);
    }
    #pragma unroll
    for (int it = 0; it < 4; ++it) __stcs(dst[it], v[it]);
}

extern "C" void kernel_launch(void* const* d_in, const int* in_sizes, int n_in,
                              void* d_out, int out_size)
{
    const float* hidden = (const float*)d_in[0];   // [1,8192,2048] f32
    const float* scores = (const float*)d_in[1];   // [1,8192] f32
    const int*   amask  = (const int*)  d_in[2];   // [1,8192] i32
    const float* keys   = (const float*)d_in[3];   // [8,1,16,8192,128] f32
    const float* values = (const float*)d_in[4];   // [8,1,16,8192,128] f32
    float* out = (float*)d_out;

    topk_kernel<<<1, 1024>>>(scores, amask, out);

    // Gather with Programmatic Dependent Launch (overlaps launch/ramp with topk)
    int blocks = (int)(TOTAL4 / 1024);             // 34816
    cudaLaunchAttribute attrs[1];
    attrs[0].id = cudaLaunchAttributeProgrammaticStreamSerialization;
    attrs[0].val.programmaticStreamSerializationAllowed = 1;

    cudaLaunchConfig_t cfg = {};
    cfg.gridDim  = dim3((unsigned)blocks, 1, 1);
    cfg.blockDim = dim3(256, 1, 1);
    cfg.dynamicSmemBytes = 0;
    cfg.stream   = 0;
    cfg.attrs    = attrs;
    cfg.numAttrs = 1;

    cudaLaunchKernelEx(&cfg, gather_kernel,
                       (const float4*)hidden,
                       (const float4*)keys,
                       (const float4*)values,
                       (float4*)out);
}